// round 1
// baseline (speedup 1.0000x reference)
#include <cuda_runtime.h>

#define D        32000
#define NV4      (D / 4)
#define THREADS  1024
#define NWARP    (THREADS / 32)
#define CCAP     6144
#define SMEM_BYTES (D * 4 + CCAP * 4)

__device__ __forceinline__ float warpSum(float v) {
#pragma unroll
    for (int o = 16; o > 0; o >>= 1) v += __shfl_down_sync(0xffffffffu, v, o);
    return v;
}
__device__ __forceinline__ float warpMax(float v) {
#pragma unroll
    for (int o = 16; o > 0; o >>= 1) v = fmaxf(v, __shfl_down_sync(0xffffffffu, v, o));
    return v;
}

struct Red {
    float red[NWARP][4];
    float bcast[4];
    int   cnt;
};

// Block-reduce 4 partial sums; results broadcast via r->bcast[0..3].
__device__ void reduce4(float s0, float s1, float s2, float s3,
                        Red* r, int lane, int wid) {
    s0 = warpSum(s0); s1 = warpSum(s1); s2 = warpSum(s2); s3 = warpSum(s3);
    if (lane == 0) {
        r->red[wid][0] = s0; r->red[wid][1] = s1;
        r->red[wid][2] = s2; r->red[wid][3] = s3;
    }
    __syncthreads();
    if (wid == 0) {
        float a = r->red[lane][0], b = r->red[lane][1];
        float c = r->red[lane][2], d = r->red[lane][3];
        a = warpSum(a); b = warpSum(b); c = warpSum(c); d = warpSum(d);
        if (lane == 0) {
            r->bcast[0] = a; r->bcast[1] = b; r->bcast[2] = c; r->bcast[3] = d;
        }
    }
    __syncthreads();
}

// Evaluate mass at the 4 interior probes over the FULL row (SMEM resident).
__device__ void mass4_full(const float* xs, float tau_lo, float width,
                           Red* r, int tid, int lane, int wid) {
    const float t1 = tau_lo + 1.0f * width;
    const float t2 = tau_lo + 2.0f * width;
    const float t3 = tau_lo + 3.0f * width;
    const float t4 = tau_lo + 4.0f * width;
    float s0 = 0.f, s1 = 0.f, s2 = 0.f, s3 = 0.f;
    const float4* x4 = (const float4*)xs;
    for (int k = tid; k < NV4; k += THREADS) {
        float4 v = x4[k];
#define ACC(c)                                                   \
        {                                                        \
            float d0 = fmaxf((c) - t1, 0.f); s0 = fmaf(d0, d0, s0); \
            float d1 = fmaxf((c) - t2, 0.f); s1 = fmaf(d1, d1, s1); \
            float d2 = fmaxf((c) - t3, 0.f); s2 = fmaf(d2, d2, s2); \
            float d3 = fmaxf((c) - t4, 0.f); s3 = fmaf(d3, d3, s3); \
        }
        ACC(v.x) ACC(v.y) ACC(v.z) ACC(v.w)
#undef ACC
    }
    reduce4(s0, s1, s2, s3, r, lane, wid);
}

__device__ __forceinline__ void update_tau(float& tau_lo, float& tau_hi,
                                           float width, const Red* r) {
    // j_best = largest j in 1..4 with mass >= 1 (reference semantics)
    int jb = 0;
    if (r->bcast[0] >= 1.0f) jb = 1;
    if (r->bcast[1] >= 1.0f) jb = 2;
    if (r->bcast[2] >= 1.0f) jb = 3;
    if (r->bcast[3] >= 1.0f) jb = 4;
    tau_lo = tau_lo + (float)jb * width;
    tau_hi = tau_lo + width;
}

__global__ __launch_bounds__(THREADS, 1)
void entmax_kernel(const float* __restrict__ X, float* __restrict__ Y) {
    extern __shared__ float smem[];
    float* xs    = smem;          // D floats: Xs = 0.5*x
    float* cvals = smem + D;      // CCAP floats: compacted active values

    __shared__ Red r;

    const int tid  = threadIdx.x;
    const int lane = tid & 31;
    const int wid  = tid >> 5;
    const size_t rowoff = (size_t)blockIdx.x * D;
    const float4* __restrict__ xin  = (const float4*)(X + rowoff);
    float4* __restrict__       yout = (float4*)(Y + rowoff);

    // ---- Pass A: load from HBM, scale by (alpha-1)=0.5, cache in SMEM, row max
    float lmax = __int_as_float(0xff800000);  // -inf
    float4* xs4 = (float4*)xs;
    for (int k = tid; k < NV4; k += THREADS) {
        float4 v = xin[k];
        v.x *= 0.5f; v.y *= 0.5f; v.z *= 0.5f; v.w *= 0.5f;
        xs4[k] = v;
        lmax = fmaxf(lmax, fmaxf(fmaxf(v.x, v.y), fmaxf(v.z, v.w)));
    }
    lmax = warpMax(lmax);
    if (lane == 0) r.red[wid][0] = lmax;
    __syncthreads();
    if (wid == 0) {
        float m = r.red[lane][0];
        m = warpMax(m);
        if (lane == 0) r.bcast[0] = m;
    }
    __syncthreads();
    const float mx = r.bcast[0];

    float tau_lo = mx - 1.0f;
    float tau_hi = mx - 0.005590169943749474f;   // (1/32000)^(alpha-1) = sqrt(1/32000)

    // ---- Iteration 1: full-row fused 4-probe pass
    {
        float width = (tau_hi - tau_lo) / 5.0f;
        mass4_full(xs, tau_lo, width, &r, tid, lane, wid);
        update_tau(tau_lo, tau_hi, width, &r);
    }

    // ---- Compaction: elements with t <= tau_lo can never contribute again
    if (tid == 0) r.cnt = 0;
    __syncthreads();
    const float thr = tau_lo;
    for (int k = tid; k < NV4; k += THREADS) {
        float4 v = xs4[k];
        if (v.x > thr) { int p = atomicAdd(&r.cnt, 1); if (p < CCAP) cvals[p] = v.x; }
        if (v.y > thr) { int p = atomicAdd(&r.cnt, 1); if (p < CCAP) cvals[p] = v.y; }
        if (v.z > thr) { int p = atomicAdd(&r.cnt, 1); if (p < CCAP) cvals[p] = v.z; }
        if (v.w > thr) { int p = atomicAdd(&r.cnt, 1); if (p < CCAP) cvals[p] = v.w; }
    }
    __syncthreads();
    const int cnt = r.cnt;

    float Ssum;
    if (cnt <= CCAP) {
        // ---- Iterations 2..5 on the compact active set (tiny)
        for (int it = 0; it < 4; it++) {
            float width = (tau_hi - tau_lo) / 5.0f;
            const float t1 = tau_lo + 1.0f * width;
            const float t2 = tau_lo + 2.0f * width;
            const float t3 = tau_lo + 3.0f * width;
            const float t4 = tau_lo + 4.0f * width;
            float s0 = 0.f, s1 = 0.f, s2 = 0.f, s3 = 0.f;
            for (int k = tid; k < cnt; k += THREADS) {
                float c = cvals[k];
                float d0 = fmaxf(c - t1, 0.f); s0 = fmaf(d0, d0, s0);
                float d1 = fmaxf(c - t2, 0.f); s1 = fmaf(d1, d1, s1);
                float d2 = fmaxf(c - t3, 0.f); s2 = fmaf(d2, d2, s2);
                float d3 = fmaxf(c - t4, 0.f); s3 = fmaf(d3, d3, s3);
            }
            reduce4(s0, s1, s2, s3, &r, lane, wid);
            update_tau(tau_lo, tau_hi, width, &r);
        }
        // ---- Final normalizer from the compact set (p==0 off-list)
        float s = 0.f;
        for (int k = tid; k < cnt; k += THREADS) {
            float d0 = fmaxf(cvals[k] - tau_lo, 0.f);
            s = fmaf(d0, d0, s);
        }
        reduce4(s, 0.f, 0.f, 0.f, &r, lane, wid);
        Ssum = r.bcast[0];
    } else {
        // ---- Fallback (never expected for this data): full-row passes
        for (int it = 0; it < 4; it++) {
            float width = (tau_hi - tau_lo) / 5.0f;
            mass4_full(xs, tau_lo, width, &r, tid, lane, wid);
            update_tau(tau_lo, tau_hi, width, &r);
        }
        float s = 0.f;
        for (int k = tid; k < NV4; k += THREADS) {
            float4 v = xs4[k];
            float d0 = fmaxf(v.x - tau_lo, 0.f); s = fmaf(d0, d0, s);
            float d1 = fmaxf(v.y - tau_lo, 0.f); s = fmaf(d1, d1, s);
            float d2 = fmaxf(v.z - tau_lo, 0.f); s = fmaf(d2, d2, s);
            float d3 = fmaxf(v.w - tau_lo, 0.f); s = fmaf(d3, d3, s);
        }
        reduce4(s, 0.f, 0.f, 0.f, &r, lane, wid);
        Ssum = r.bcast[0];
    }

    const float invS = 1.0f / Ssum;
    const float tau  = tau_lo;

    // ---- Final write: p = relu(t - tau)^2 / S
    for (int k = tid; k < NV4; k += THREADS) {
        float4 v = xs4[k];
        float4 o;
        float d0 = fmaxf(v.x - tau, 0.f); o.x = d0 * d0 * invS;
        float d1 = fmaxf(v.y - tau, 0.f); o.y = d1 * d1 * invS;
        float d2 = fmaxf(v.z - tau, 0.f); o.z = d2 * d2 * invS;
        float d3 = fmaxf(v.w - tau, 0.f); o.w = d3 * d3 * invS;
        yout[k] = o;
    }
}

extern "C" void kernel_launch(void* const* d_in, const int* in_sizes, int n_in,
                              void* d_out, int out_size) {
    const float* X = (const float*)d_in[0];
    float* Y = (float*)d_out;
    const int rows = in_sizes[0] / D;   // 8192 for (4, 2048, 32000)
    cudaFuncSetAttribute(entmax_kernel,
                         cudaFuncAttributeMaxDynamicSharedMemorySize, SMEM_BYTES);
    entmax_kernel<<<rows, THREADS, SMEM_BYTES>>>(X, Y);
}